// round 4
// baseline (speedup 1.0000x reference)
#include <cuda_runtime.h>
#include <cstdint>
#include <cstddef>

// ---------------------------------------------------------------------------
// Problem dims (fixed by the reference)
// ---------------------------------------------------------------------------
#define Bb   2
#define Ss   4096
#define Ff   768
#define Hh   12
#define Dd   64
#define ROWS (Bb * Ss)          // 8192 token rows
#define NQKV (3 * Ff)           // 2304

// ---------------------------------------------------------------------------
// Scratch (device globals: allocation-free rule)
// ---------------------------------------------------------------------------
__device__ float g_q[ROWS * Ff];     // [B,S,H,D] flattened
__device__ float g_k[ROWS * Ff];
__device__ float g_v[ROWS * Ff];
__device__ float g_attn[ROWS * Ff];  // attention output [B,S,H,D]

// ---------------------------------------------------------------------------
// Kernel 1 & 3: 128x128x8 register-tiled SGEMM, 256 threads, 8x8 per thread.
// mode 0: C is ignored; result split by column into g_q / g_k / g_v (N==2304)
// mode 1: C[row*N + col] = acc + bias[col]
// ---------------------------------------------------------------------------
__global__ __launch_bounds__(256)
void sgemm128(const float* __restrict__ A, const float* __restrict__ Bm,
              const float* __restrict__ bias, float* __restrict__ C,
              int M, int N, int K, int mode)
{
    constexpr int BM = 128, BN = 128, BK = 8;
    __shared__ float As[BK][BM];   // transposed A tile
    __shared__ float Bs[BK][BN];

    const int tid  = threadIdx.x;
    const int tcol = tid & 15;     // 16 col groups * 8
    const int trow = tid >> 4;     // 16 row groups * 8
    const int rowBase = blockIdx.y * BM;
    const int colBase = blockIdx.x * BN;

    // A tile loaders: 128 rows x 8 k, float4 each
    const int aRow = tid >> 1;
    const int aCol = (tid & 1) * 4;
    // B tile loaders: 8 k x 128 cols, float4 each
    const int bRow = tid >> 5;
    const int bCol = (tid & 31) * 4;

    const float* Aptr = A + (size_t)(rowBase + aRow) * K + aCol;
    const float* Bptr = Bm + (size_t)bRow * N + colBase + bCol;

    float acc[8][8];
#pragma unroll
    for (int i = 0; i < 8; i++)
#pragma unroll
        for (int j = 0; j < 8; j++) acc[i][j] = 0.f;

    for (int k0 = 0; k0 < K; k0 += BK) {
        float4 av = *(const float4*)(Aptr + k0);
        As[aCol + 0][aRow] = av.x;
        As[aCol + 1][aRow] = av.y;
        As[aCol + 2][aRow] = av.z;
        As[aCol + 3][aRow] = av.w;
        float4 bv = *(const float4*)(Bptr + (size_t)k0 * N);
        *(float4*)&Bs[bRow][bCol] = bv;
        __syncthreads();

#pragma unroll
        for (int k = 0; k < BK; k++) {
            float4 a0 = *(const float4*)&As[k][trow * 8];
            float4 a1 = *(const float4*)&As[k][trow * 8 + 4];
            float4 b0 = *(const float4*)&Bs[k][tcol * 8];
            float4 b1 = *(const float4*)&Bs[k][tcol * 8 + 4];
            float ra[8] = {a0.x, a0.y, a0.z, a0.w, a1.x, a1.y, a1.z, a1.w};
            float rb[8] = {b0.x, b0.y, b0.z, b0.w, b1.x, b1.y, b1.z, b1.w};
#pragma unroll
            for (int i = 0; i < 8; i++)
#pragma unroll
                for (int j = 0; j < 8; j++)
                    acc[i][j] = fmaf(ra[i], rb[j], acc[i][j]);
        }
        __syncthreads();
    }

    if (mode == 0) {
        // split QKV columns: each 128-wide column tile lies in exactly one segment
        const int seg = colBase / Ff;                 // 0:q 1:k 2:v
        const int localBase = colBase - seg * Ff;
        float* dst = (seg == 0) ? g_q : (seg == 1) ? g_k : g_v;
#pragma unroll
        for (int i = 0; i < 8; i++) {
            const int r = rowBase + trow * 8 + i;
#pragma unroll
            for (int j4 = 0; j4 < 8; j4 += 4) {
                const int c = tcol * 8 + j4;
                float4 v;
                v.x = acc[i][j4 + 0] + bias[colBase + c + 0];
                v.y = acc[i][j4 + 1] + bias[colBase + c + 1];
                v.z = acc[i][j4 + 2] + bias[colBase + c + 2];
                v.w = acc[i][j4 + 3] + bias[colBase + c + 3];
                *(float4*)(dst + (size_t)r * Ff + localBase + c) = v;
            }
        }
    } else {
#pragma unroll
        for (int i = 0; i < 8; i++) {
            const int r = rowBase + trow * 8 + i;
#pragma unroll
            for (int j4 = 0; j4 < 8; j4 += 4) {
                const int c = tcol * 8 + j4;
                float4 v;
                v.x = acc[i][j4 + 0] + bias[colBase + c + 0];
                v.y = acc[i][j4 + 1] + bias[colBase + c + 1];
                v.z = acc[i][j4 + 2] + bias[colBase + c + 2];
                v.w = acc[i][j4 + 3] + bias[colBase + c + 3];
                *(float4*)(C + (size_t)r * N + colBase + c) = v;
            }
        }
    }
}

// ---------------------------------------------------------------------------
// Kernel 2: flash attention, causal.
// CTA: 128 query rows, loop over 64-key tiles (2*qt+2 of them).
// 256 threads as 16(ty: 8 q-rows each) x 16(tx: 4 keys / 4 d-cols each).
// Smem layouts (pitches chosen for conflict behavior):
//   Qt[d][q]  pitch 132 (float4 reads)
//   Kt[d][k]  pitch 65  (scalar reads, 2-way worst)
//   Vs[k][d]  pitch 65
//   Pt[k][q]  pitch 129
// ---------------------------------------------------------------------------
#define BQ  128
#define BKT 64
#define PQ  132
#define PK  65
#define PV2 65
#define PP  129
#define ATTN_SMEM_FLOATS (64 * PQ + 64 * PK + 64 * PV2 + 64 * PP + 64)
#define ATTN_SMEM_BYTES  (ATTN_SMEM_FLOATS * 4)

__global__ __launch_bounds__(256)
void flash_attn_kernel(const unsigned char* __restrict__ padmask)
{
    extern __shared__ float sm[];
    float* Qt     = sm;                 // [64][PQ]
    float* Kt     = Qt + 64 * PQ;       // [64][PK]
    float* Vs     = Kt + 64 * PK;       // [64][PV2]
    float* Pt     = Vs + 64 * PV2;      // [64][PP]
    float* padAdd = Pt + 64 * PP;       // [64]

    const int tid = threadIdx.x;
    const int tx  = tid & 15;
    const int ty  = tid >> 4;

    const int bh = blockIdx.y;
    const int b  = bh / Hh;
    const int h  = bh % Hh;
    // reverse q-tile order: longest CTAs first (causal imbalance)
    const int qt    = gridDim.x - 1 - blockIdx.x;
    const int qBase = qt * BQ;

    const float* Qg = g_q + (size_t)b * Ss * Ff + h * Dd;
    const float* Kg = g_k + (size_t)b * Ss * Ff + h * Dd;
    const float* Vg = g_v + (size_t)b * Ss * Ff + h * Dd;

    // load Q tile transposed: Qt[d][qrow]
#pragma unroll
    for (int r = 0; r < 8; r++) {
        const int idx = tid + r * 256;           // 2048 float4
        const int qr  = idx >> 4;                // 0..127
        const int d4  = (idx & 15) * 4;
        float4 v = *(const float4*)(Qg + (size_t)(qBase + qr) * Ff + d4);
        Qt[(d4 + 0) * PQ + qr] = v.x;
        Qt[(d4 + 1) * PQ + qr] = v.y;
        Qt[(d4 + 2) * PQ + qr] = v.z;
        Qt[(d4 + 3) * PQ + qr] = v.w;
    }

    float m[8], l[8], o[8][4];
#pragma unroll
    for (int i = 0; i < 8; i++) {
        m[i] = -1e30f;
        l[i] = 0.f;
#pragma unroll
        for (int j = 0; j < 4; j++) o[i][j] = 0.f;
    }

    const float SC = 0.125f;   // 1/sqrt(64)
    const int nkt = (qBase + BQ) / BKT;   // 2*qt + 2 key tiles (causal)

    for (int kt = 0; kt < nkt; kt++) {
        const int kBase = kt * BKT;
        __syncthreads();   // previous tile's Kt/Vs/Pt fully consumed

        // load K transposed + V natural
#pragma unroll
        for (int r = 0; r < 4; r++) {
            const int idx = tid + r * 256;       // 1024 float4
            const int kr  = idx >> 4;            // 0..63
            const int d4  = (idx & 15) * 4;
            float4 kv = *(const float4*)(Kg + (size_t)(kBase + kr) * Ff + d4);
            Kt[(d4 + 0) * PK + kr] = kv.x;
            Kt[(d4 + 1) * PK + kr] = kv.y;
            Kt[(d4 + 2) * PK + kr] = kv.z;
            Kt[(d4 + 3) * PK + kr] = kv.w;
            float4 vv = *(const float4*)(Vg + (size_t)(kBase + kr) * Ff + d4);
            Vs[kr * PV2 + d4 + 0] = vv.x;
            Vs[kr * PV2 + d4 + 1] = vv.y;
            Vs[kr * PV2 + d4 + 2] = vv.z;
            Vs[kr * PV2 + d4 + 3] = vv.w;
        }
        if (tid < BKT)
            padAdd[tid] = padmask[(size_t)b * Ss + kBase + tid] ? -1e30f : 0.f;
        __syncthreads();

        // ---- S = Q K^T (8x4 per thread) ----
        float s[8][4];
#pragma unroll
        for (int i = 0; i < 8; i++)
#pragma unroll
            for (int j = 0; j < 4; j++) s[i][j] = 0.f;

#pragma unroll 8
        for (int d = 0; d < 64; d++) {
            float4 q0 = *(const float4*)(Qt + d * PQ + ty * 8);
            float4 q1 = *(const float4*)(Qt + d * PQ + ty * 8 + 4);
            float rq[8] = {q0.x, q0.y, q0.z, q0.w, q1.x, q1.y, q1.z, q1.w};
            float rk0 = Kt[d * PK + tx * 4 + 0];
            float rk1 = Kt[d * PK + tx * 4 + 1];
            float rk2 = Kt[d * PK + tx * 4 + 2];
            float rk3 = Kt[d * PK + tx * 4 + 3];
#pragma unroll
            for (int i = 0; i < 8; i++) {
                s[i][0] = fmaf(rq[i], rk0, s[i][0]);
                s[i][1] = fmaf(rq[i], rk1, s[i][1]);
                s[i][2] = fmaf(rq[i], rk2, s[i][2]);
                s[i][3] = fmaf(rq[i], rk3, s[i][3]);
            }
        }

        // ---- scale + padding + causal mask ----
        float pj[4];
#pragma unroll
        for (int j = 0; j < 4; j++) pj[j] = padAdd[tx * 4 + j];

        if (kBase + BKT - 1 > qBase) {   // tile touches the diagonal
#pragma unroll
            for (int i = 0; i < 8; i++) {
                const int qg = qBase + ty * 8 + i;
#pragma unroll
                for (int j = 0; j < 4; j++) {
                    const int kg = kBase + tx * 4 + j;
                    float v = fmaf(s[i][j], SC, pj[j]);
                    s[i][j] = (kg > qg) ? -1e30f : v;
                }
            }
        } else {
#pragma unroll
            for (int i = 0; i < 8; i++)
#pragma unroll
                for (int j = 0; j < 4; j++)
                    s[i][j] = fmaf(s[i][j], SC, pj[j]);
        }

        // ---- online softmax (rows shared across tx: shuffle over 16 lanes) ----
#pragma unroll
        for (int i = 0; i < 8; i++) {
            float mt = fmaxf(fmaxf(s[i][0], s[i][1]), fmaxf(s[i][2], s[i][3]));
#pragma unroll
            for (int off = 8; off >= 1; off >>= 1)
                mt = fmaxf(mt, __shfl_xor_sync(0xffffffffu, mt, off));
            const float mnew = fmaxf(m[i], mt);
            const float corr = __expf(m[i] - mnew);
            m[i] = mnew;
            float rs = 0.f;
#pragma unroll
            for (int j = 0; j < 4; j++) {
                const float p = __expf(s[i][j] - mnew);
                s[i][j] = p;
                rs += p;
            }
#pragma unroll
            for (int off = 8; off >= 1; off >>= 1)
                rs += __shfl_xor_sync(0xffffffffu, rs, off);
            l[i] = l[i] * corr + rs;
#pragma unroll
            for (int j = 0; j < 4; j++) o[i][j] *= corr;
        }

        // ---- stash P, then O += P V ----
#pragma unroll
        for (int i = 0; i < 8; i++)
#pragma unroll
            for (int j = 0; j < 4; j++)
                Pt[(tx * 4 + j) * PP + ty * 8 + i] = s[i][j];
        __syncthreads();

#pragma unroll 8
        for (int k = 0; k < 64; k++) {
            const float rv0 = Vs[k * PV2 + tx * 4 + 0];
            const float rv1 = Vs[k * PV2 + tx * 4 + 1];
            const float rv2 = Vs[k * PV2 + tx * 4 + 2];
            const float rv3 = Vs[k * PV2 + tx * 4 + 3];
#pragma unroll
            for (int i = 0; i < 8; i++) {
                const float rp = Pt[k * PP + ty * 8 + i];
                o[i][0] = fmaf(rp, rv0, o[i][0]);
                o[i][1] = fmaf(rp, rv1, o[i][1]);
                o[i][2] = fmaf(rp, rv2, o[i][2]);
                o[i][3] = fmaf(rp, rv3, o[i][3]);
            }
        }
    }

    // ---- finalize: O /= l, write [B,S,H,D] ----
#pragma unroll
    for (int i = 0; i < 8; i++) {
        const float inv = 1.0f / l[i];
        const int qg = qBase + ty * 8 + i;
        float4 v = make_float4(o[i][0] * inv, o[i][1] * inv,
                               o[i][2] * inv, o[i][3] * inv);
        *(float4*)(g_attn + (size_t)(b * Ss + qg) * Ff + h * Dd + tx * 4) = v;
    }
}

// ---------------------------------------------------------------------------
// Launch: QKV gemm -> flash attention -> output gemm (one default stream)
// ---------------------------------------------------------------------------
extern "C" void kernel_launch(void* const* d_in, const int* in_sizes, int n_in,
                              void* d_out, int out_size)
{
    (void)in_sizes; (void)n_in; (void)out_size;
    const float*         x    = (const float*)d_in[0];
    const unsigned char* pad  = (const unsigned char*)d_in[1];
    const float*         Wqkv = (const float*)d_in[2];
    const float*         bqkv = (const float*)d_in[3];
    const float*         Wout = (const float*)d_in[4];
    const float*         bout = (const float*)d_in[5];
    float*               out  = (float*)d_out;

    // 1) QKV projection: [8192,768] @ [768,2304], split-written to g_q/g_k/g_v
    {
        dim3 grid(NQKV / 128, ROWS / 128);   // (18, 64)
        sgemm128<<<grid, 256>>>(x, Wqkv, bqkv, nullptr, ROWS, NQKV, Ff, 0);
    }

    // 2) causal flash attention -> g_attn
    {
        cudaFuncSetAttribute(flash_attn_kernel,
                             cudaFuncAttributeMaxDynamicSharedMemorySize,
                             ATTN_SMEM_BYTES);
        dim3 grid(Ss / BQ, Bb * Hh);         // (32, 24)
        flash_attn_kernel<<<grid, 256, ATTN_SMEM_BYTES>>>(pad);
    }

    // 3) output projection: g_attn @ Wout + bout -> d_out
    {
        float* attnPtr = nullptr;
        cudaGetSymbolAddress((void**)&attnPtr, g_attn);
        dim3 grid(Ff / 128, ROWS / 128);     // (6, 64)
        sgemm128<<<grid, 256>>>(attnPtr, Wout, bout, out, ROWS, Ff, Ff, 1);
    }
}

// round 6
// speedup vs baseline: 1.0064x; 1.0064x over previous
#include <cuda_runtime.h>
#include <cstdint>
#include <cstddef>

// ---------------------------------------------------------------------------
// Problem dims (fixed by the reference)
// ---------------------------------------------------------------------------
#define Bb   2
#define Ss   4096
#define Ff   768
#define Hh   12
#define Dd   64
#define ROWS (Bb * Ss)          // 8192 token rows
#define NQKV (3 * Ff)           // 2304

// ---------------------------------------------------------------------------
// Scratch (device globals: allocation-free rule)
// ---------------------------------------------------------------------------
__device__ float g_q[ROWS * Ff];     // [B,S,H,D] flattened
__device__ float g_k[ROWS * Ff];
__device__ float g_v[ROWS * Ff];
__device__ float g_attn[ROWS * Ff];  // attention output [B,S,H,D]

// ---------------------------------------------------------------------------
// Kernel 1 & 3: 128x128x8 register-tiled SGEMM, 256 threads, 8x8 per thread.
// mode 0: C is ignored; result split by column into g_q / g_k / g_v (N==2304)
// mode 1: C[row*N + col] = acc + bias[col]
// ---------------------------------------------------------------------------
__global__ __launch_bounds__(256)
void sgemm128(const float* __restrict__ A, const float* __restrict__ Bm,
              const float* __restrict__ bias, float* __restrict__ C,
              int M, int N, int K, int mode)
{
    constexpr int BM = 128, BN = 128, BK = 8;
    __shared__ float As[BK][BM];   // transposed A tile
    __shared__ float Bs[BK][BN];

    const int tid  = threadIdx.x;
    const int tcol = tid & 15;     // 16 col groups * 8
    const int trow = tid >> 4;     // 16 row groups * 8
    const int rowBase = blockIdx.y * BM;
    const int colBase = blockIdx.x * BN;

    // A tile loaders: 128 rows x 8 k, float4 each
    const int aRow = tid >> 1;
    const int aCol = (tid & 1) * 4;
    // B tile loaders: 8 k x 128 cols, float4 each
    const int bRow = tid >> 5;
    const int bCol = (tid & 31) * 4;

    const float* Aptr = A + (size_t)(rowBase + aRow) * K + aCol;
    const float* Bptr = Bm + (size_t)bRow * N + colBase + bCol;

    float acc[8][8];
#pragma unroll
    for (int i = 0; i < 8; i++)
#pragma unroll
        for (int j = 0; j < 8; j++) acc[i][j] = 0.f;

    for (int k0 = 0; k0 < K; k0 += BK) {
        float4 av = *(const float4*)(Aptr + k0);
        As[aCol + 0][aRow] = av.x;
        As[aCol + 1][aRow] = av.y;
        As[aCol + 2][aRow] = av.z;
        As[aCol + 3][aRow] = av.w;
        float4 bv = *(const float4*)(Bptr + (size_t)k0 * N);
        *(float4*)&Bs[bRow][bCol] = bv;
        __syncthreads();

#pragma unroll
        for (int k = 0; k < BK; k++) {
            float4 a0 = *(const float4*)&As[k][trow * 8];
            float4 a1 = *(const float4*)&As[k][trow * 8 + 4];
            float4 b0 = *(const float4*)&Bs[k][tcol * 8];
            float4 b1 = *(const float4*)&Bs[k][tcol * 8 + 4];
            float ra[8] = {a0.x, a0.y, a0.z, a0.w, a1.x, a1.y, a1.z, a1.w};
            float rb[8] = {b0.x, b0.y, b0.z, b0.w, b1.x, b1.y, b1.z, b1.w};
#pragma unroll
            for (int i = 0; i < 8; i++)
#pragma unroll
                for (int j = 0; j < 8; j++)
                    acc[i][j] = fmaf(ra[i], rb[j], acc[i][j]);
        }
        __syncthreads();
    }

    if (mode == 0) {
        // split QKV columns: each 128-wide column tile lies in exactly one segment
        const int seg = colBase / Ff;                 // 0:q 1:k 2:v
        const int localBase = colBase - seg * Ff;
        float* dst = (seg == 0) ? g_q : (seg == 1) ? g_k : g_v;
#pragma unroll
        for (int i = 0; i < 8; i++) {
            const int r = rowBase + trow * 8 + i;
#pragma unroll
            for (int j4 = 0; j4 < 8; j4 += 4) {
                const int c = tcol * 8 + j4;
                float4 v;
                v.x = acc[i][j4 + 0] + bias[colBase + c + 0];
                v.y = acc[i][j4 + 1] + bias[colBase + c + 1];
                v.z = acc[i][j4 + 2] + bias[colBase + c + 2];
                v.w = acc[i][j4 + 3] + bias[colBase + c + 3];
                *(float4*)(dst + (size_t)r * Ff + localBase + c) = v;
            }
        }
    } else {
#pragma unroll
        for (int i = 0; i < 8; i++) {
            const int r = rowBase + trow * 8 + i;
#pragma unroll
            for (int j4 = 0; j4 < 8; j4 += 4) {
                const int c = tcol * 8 + j4;
                float4 v;
                v.x = acc[i][j4 + 0] + bias[colBase + c + 0];
                v.y = acc[i][j4 + 1] + bias[colBase + c + 1];
                v.z = acc[i][j4 + 2] + bias[colBase + c + 2];
                v.w = acc[i][j4 + 3] + bias[colBase + c + 3];
                *(float4*)(C + (size_t)r * N + colBase + c) = v;
            }
        }
    }
}

// ---------------------------------------------------------------------------
// Kernel 2: flash attention, causal.
// CTA: 128 query rows, loop over 64-key tiles (2*qt+2 of them).
// 256 threads as 16(ty: 8 q-rows each) x 16(tx: 4 keys / 4 d-cols each).
// Smem layouts (pitches chosen for conflict behavior):
//   Qt[d][q]  pitch 132 (float4 reads)
//   Kt[d][k]  pitch 65  (scalar reads, 2-way worst)
//   Vs[k][d]  pitch 65
//   Pt[k][q]  pitch 129
// ---------------------------------------------------------------------------
#define BQ  128
#define BKT 64
#define PQ  132
#define PK  65
#define PV2 65
#define PP  129
#define ATTN_SMEM_FLOATS (64 * PQ + 64 * PK + 64 * PV2 + 64 * PP + 64)
#define ATTN_SMEM_BYTES  (ATTN_SMEM_FLOATS * 4)

__global__ __launch_bounds__(256)
void flash_attn_kernel(const unsigned char* __restrict__ padmask)
{
    extern __shared__ float sm[];
    float* Qt     = sm;                 // [64][PQ]
    float* Kt     = Qt + 64 * PQ;       // [64][PK]
    float* Vs     = Kt + 64 * PK;       // [64][PV2]
    float* Pt     = Vs + 64 * PV2;      // [64][PP]
    float* padAdd = Pt + 64 * PP;       // [64]

    const int tid = threadIdx.x;
    const int tx  = tid & 15;
    const int ty  = tid >> 4;

    const int bh = blockIdx.y;
    const int b  = bh / Hh;
    const int h  = bh % Hh;
    // reverse q-tile order: longest CTAs first (causal imbalance)
    const int qt    = gridDim.x - 1 - blockIdx.x;
    const int qBase = qt * BQ;

    const float* Qg = g_q + (size_t)b * Ss * Ff + h * Dd;
    const float* Kg = g_k + (size_t)b * Ss * Ff + h * Dd;
    const float* Vg = g_v + (size_t)b * Ss * Ff + h * Dd;

    // load Q tile transposed: Qt[d][qrow]
#pragma unroll
    for (int r = 0; r < 8; r++) {
        const int idx = tid + r * 256;           // 2048 float4
        const int qr  = idx >> 4;                // 0..127
        const int d4  = (idx & 15) * 4;
        float4 v = *(const float4*)(Qg + (size_t)(qBase + qr) * Ff + d4);
        Qt[(d4 + 0) * PQ + qr] = v.x;
        Qt[(d4 + 1) * PQ + qr] = v.y;
        Qt[(d4 + 2) * PQ + qr] = v.z;
        Qt[(d4 + 3) * PQ + qr] = v.w;
    }

    float m[8], l[8], o[8][4];
#pragma unroll
    for (int i = 0; i < 8; i++) {
        m[i] = -1e30f;
        l[i] = 0.f;
#pragma unroll
        for (int j = 0; j < 4; j++) o[i][j] = 0.f;
    }

    const float SC = 0.125f;   // 1/sqrt(64)
    const int nkt = (qBase + BQ) / BKT;   // 2*qt + 2 key tiles (causal)

    for (int kt = 0; kt < nkt; kt++) {
        const int kBase = kt * BKT;
        __syncthreads();   // previous tile's Kt/Vs/Pt fully consumed

        // load K transposed + V natural
#pragma unroll
        for (int r = 0; r < 4; r++) {
            const int idx = tid + r * 256;       // 1024 float4
            const int kr  = idx >> 4;            // 0..63
            const int d4  = (idx & 15) * 4;
            float4 kv = *(const float4*)(Kg + (size_t)(kBase + kr) * Ff + d4);
            Kt[(d4 + 0) * PK + kr] = kv.x;
            Kt[(d4 + 1) * PK + kr] = kv.y;
            Kt[(d4 + 2) * PK + kr] = kv.z;
            Kt[(d4 + 3) * PK + kr] = kv.w;
            float4 vv = *(const float4*)(Vg + (size_t)(kBase + kr) * Ff + d4);
            Vs[kr * PV2 + d4 + 0] = vv.x;
            Vs[kr * PV2 + d4 + 1] = vv.y;
            Vs[kr * PV2 + d4 + 2] = vv.z;
            Vs[kr * PV2 + d4 + 3] = vv.w;
        }
        if (tid < BKT)
            padAdd[tid] = padmask[(size_t)b * Ss + kBase + tid] ? -1e30f : 0.f;
        __syncthreads();

        // ---- S = Q K^T (8x4 per thread) ----
        float s[8][4];
#pragma unroll
        for (int i = 0; i < 8; i++)
#pragma unroll
            for (int j = 0; j < 4; j++) s[i][j] = 0.f;

#pragma unroll 8
        for (int d = 0; d < 64; d++) {
            float4 q0 = *(const float4*)(Qt + d * PQ + ty * 8);
            float4 q1 = *(const float4*)(Qt + d * PQ + ty * 8 + 4);
            float rq[8] = {q0.x, q0.y, q0.z, q0.w, q1.x, q1.y, q1.z, q1.w};
            float rk0 = Kt[d * PK + tx * 4 + 0];
            float rk1 = Kt[d * PK + tx * 4 + 1];
            float rk2 = Kt[d * PK + tx * 4 + 2];
            float rk3 = Kt[d * PK + tx * 4 + 3];
#pragma unroll
            for (int i = 0; i < 8; i++) {
                s[i][0] = fmaf(rq[i], rk0, s[i][0]);
                s[i][1] = fmaf(rq[i], rk1, s[i][1]);
                s[i][2] = fmaf(rq[i], rk2, s[i][2]);
                s[i][3] = fmaf(rq[i], rk3, s[i][3]);
            }
        }

        // ---- scale + padding + causal mask ----
        float pj[4];
#pragma unroll
        for (int j = 0; j < 4; j++) pj[j] = padAdd[tx * 4 + j];

        if (kBase + BKT - 1 > qBase) {   // tile touches the diagonal
#pragma unroll
            for (int i = 0; i < 8; i++) {
                const int qg = qBase + ty * 8 + i;
#pragma unroll
                for (int j = 0; j < 4; j++) {
                    const int kg = kBase + tx * 4 + j;
                    float v = fmaf(s[i][j], SC, pj[j]);
                    s[i][j] = (kg > qg) ? -1e30f : v;
                }
            }
        } else {
#pragma unroll
            for (int i = 0; i < 8; i++)
#pragma unroll
                for (int j = 0; j < 4; j++)
                    s[i][j] = fmaf(s[i][j], SC, pj[j]);
        }

        // ---- online softmax (rows shared across tx: shuffle over 16 lanes) ----
#pragma unroll
        for (int i = 0; i < 8; i++) {
            float mt = fmaxf(fmaxf(s[i][0], s[i][1]), fmaxf(s[i][2], s[i][3]));
#pragma unroll
            for (int off = 8; off >= 1; off >>= 1)
                mt = fmaxf(mt, __shfl_xor_sync(0xffffffffu, mt, off));
            const float mnew = fmaxf(m[i], mt);
            const float corr = __expf(m[i] - mnew);
            m[i] = mnew;
            float rs = 0.f;
#pragma unroll
            for (int j = 0; j < 4; j++) {
                const float p = __expf(s[i][j] - mnew);
                s[i][j] = p;
                rs += p;
            }
#pragma unroll
            for (int off = 8; off >= 1; off >>= 1)
                rs += __shfl_xor_sync(0xffffffffu, rs, off);
            l[i] = l[i] * corr + rs;
#pragma unroll
            for (int j = 0; j < 4; j++) o[i][j] *= corr;
        }

        // ---- stash P, then O += P V ----
#pragma unroll
        for (int i = 0; i < 8; i++)
#pragma unroll
            for (int j = 0; j < 4; j++)
                Pt[(tx * 4 + j) * PP + ty * 8 + i] = s[i][j];
        __syncthreads();

#pragma unroll 8
        for (int k = 0; k < 64; k++) {
            const float rv0 = Vs[k * PV2 + tx * 4 + 0];
            const float rv1 = Vs[k * PV2 + tx * 4 + 1];
            const float rv2 = Vs[k * PV2 + tx * 4 + 2];
            const float rv3 = Vs[k * PV2 + tx * 4 + 3];
#pragma unroll
            for (int i = 0; i < 8; i++) {
                const float rp = Pt[k * PP + ty * 8 + i];
                o[i][0] = fmaf(rp, rv0, o[i][0]);
                o[i][1] = fmaf(rp, rv1, o[i][1]);
                o[i][2] = fmaf(rp, rv2, o[i][2]);
                o[i][3] = fmaf(rp, rv3, o[i][3]);
            }
        }
    }

    // ---- finalize: O /= l, write [B,S,H,D] ----
#pragma unroll
    for (int i = 0; i < 8; i++) {
        const float inv = 1.0f / l[i];
        const int qg = qBase + ty * 8 + i;
        float4 v = make_float4(o[i][0] * inv, o[i][1] * inv,
                               o[i][2] * inv, o[i][3] * inv);
        *(float4*)(g_attn + (size_t)(b * Ss + qg) * Ff + h * Dd + tx * 4) = v;
    }
}

// ---------------------------------------------------------------------------
// Launch: QKV gemm -> flash attention -> output gemm (one default stream)
// ---------------------------------------------------------------------------
extern "C" void kernel_launch(void* const* d_in, const int* in_sizes, int n_in,
                              void* d_out, int out_size)
{
    (void)in_sizes; (void)n_in; (void)out_size;
    const float*         x    = (const float*)d_in[0];
    const unsigned char* pad  = (const unsigned char*)d_in[1];
    const float*         Wqkv = (const float*)d_in[2];
    const float*         bqkv = (const float*)d_in[3];
    const float*         Wout = (const float*)d_in[4];
    const float*         bout = (const float*)d_in[5];
    float*               out  = (float*)d_out;

    // 1) QKV projection: [8192,768] @ [768,2304], split-written to g_q/g_k/g_v
    {
        dim3 grid(NQKV / 128, ROWS / 128);   // (18, 64)
        sgemm128<<<grid, 256>>>(x, Wqkv, bqkv, nullptr, ROWS, NQKV, Ff, 0);
    }

    // 2) causal flash attention -> g_attn
    {
        cudaFuncSetAttribute(flash_attn_kernel,
                             cudaFuncAttributeMaxDynamicSharedMemorySize,
                             ATTN_SMEM_BYTES);
        dim3 grid(Ss / BQ, Bb * Hh);         // (32, 24)
        flash_attn_kernel<<<grid, 256, ATTN_SMEM_BYTES>>>(pad);
    }

    // 3) output projection: g_attn @ Wout + bout -> d_out
    {
        float* attnPtr = nullptr;
        cudaGetSymbolAddress((void**)&attnPtr, g_attn);
        dim3 grid(Ff / 128, ROWS / 128);     // (6, 64)
        sgemm128<<<grid, 256>>>(attnPtr, Wout, bout, out, ROWS, Ff, Ff, 1);
    }
}

// round 8
// speedup vs baseline: 2.6466x; 2.6298x over previous
#include <cuda_runtime.h>
#include <cstdint>
#include <cstddef>

// ---------------------------------------------------------------------------
// Problem dims (fixed by the reference)
// ---------------------------------------------------------------------------
#define Bb   2
#define Ss   4096
#define Ff   768
#define Hh   12
#define Dd   64
#define ROWS (Bb * Ss)          // 8192 token rows
#define NQKV (3 * Ff)           // 2304

// ---------------------------------------------------------------------------
// Scratch (device globals: allocation-free rule)
// ---------------------------------------------------------------------------
__device__ float g_q[ROWS * Ff];     // [B,S,H,D] flattened
__device__ float g_k[ROWS * Ff];
__device__ float g_v[ROWS * Ff];
__device__ float g_attn[ROWS * Ff];  // attention output [B,S,H,D]

// ---------------------------------------------------------------------------
// TF32 helpers
// ---------------------------------------------------------------------------
__device__ __forceinline__ unsigned f2tf(float f) {
    unsigned u;
    asm("cvt.rna.tf32.f32 %0, %1;" : "=r"(u) : "f"(f));
    return u;
}

// D += A(16x8) * B(8x8), tf32 inputs, fp32 accum
__device__ __forceinline__ void mma8(float* c, const unsigned* a, const unsigned* b) {
    asm volatile(
        "mma.sync.aligned.m16n8k8.row.col.f32.tf32.tf32.f32 "
        "{%0,%1,%2,%3}, {%4,%5,%6,%7}, {%8,%9}, {%0,%1,%2,%3};"
        : "+f"(c[0]), "+f"(c[1]), "+f"(c[2]), "+f"(c[3])
        : "r"(a[0]), "r"(a[1]), "r"(a[2]), "r"(a[3]), "r"(b[0]), "r"(b[1]));
}

// ---------------------------------------------------------------------------
// Kernel 1 & 3: TF32 tensor-core GEMM, 128x128 tile, BK=8, 256 threads.
// Warp layout: 2(M: 64 rows) x 4(N: 32 cols); per warp 4x4 m16n8k8 tiles.
// Smem pitches: As[m][k] pitch 12 (12b+a distinct mod 32 -> conflict-free),
//               Bs[k][n] pitch 136 (8a+b distinct -> conflict-free).
// mode 0: split columns into g_q/g_k/g_v (N==2304); mode 1: C = acc + bias.
// ---------------------------------------------------------------------------
__global__ __launch_bounds__(256)
void gemm_tf32(const float* __restrict__ A, const float* __restrict__ Bm,
               const float* __restrict__ bias, float* __restrict__ C,
               int K, int N, int mode)
{
    __shared__ unsigned As[128][12];
    __shared__ unsigned Bs[8][136];

    const int tid  = threadIdx.x;
    const int lane = tid & 31;
    const int wid  = tid >> 5;
    const int gid  = lane >> 2;      // 0..7
    const int tig  = lane & 3;       // 0..3
    const int warpM = wid & 1;
    const int warpN = wid >> 1;

    const int rowBase = blockIdx.y * 128;
    const int colBase = blockIdx.x * 128;

    // loaders
    const int aRow = tid >> 1;
    const int aCol = (tid & 1) * 4;
    const int bRow = tid >> 5;
    const int bCol = (tid & 31) * 4;
    const float* Aptr = A + (size_t)(rowBase + aRow) * K + aCol;
    const float* Bptr = Bm + (size_t)bRow * N + colBase + bCol;

    float acc[4][4][4];
#pragma unroll
    for (int mt = 0; mt < 4; mt++)
#pragma unroll
        for (int nt = 0; nt < 4; nt++)
#pragma unroll
            for (int r = 0; r < 4; r++) acc[mt][nt][r] = 0.f;

    // first tile -> smem
    {
        float4 av = *(const float4*)Aptr;
        float4 bv = *(const float4*)Bptr;
        uint4 ta = make_uint4(f2tf(av.x), f2tf(av.y), f2tf(av.z), f2tf(av.w));
        uint4 tb = make_uint4(f2tf(bv.x), f2tf(bv.y), f2tf(bv.z), f2tf(bv.w));
        *(uint4*)&As[aRow][aCol] = ta;
        *(uint4*)&Bs[bRow][bCol] = tb;
    }

    const int nIter = K / 8;
#pragma unroll 1
    for (int it = 0; it < nIter; it++) {
        __syncthreads();   // smem tile visible

        float4 nav, nbv;
        const bool more = (it + 1 < nIter);
        if (more) {
            nav = *(const float4*)(Aptr + (it + 1) * 8);
            nbv = *(const float4*)(Bptr + (size_t)(it + 1) * 8 * N);
        }

        unsigned af[4][4], bf[4][2];
#pragma unroll
        for (int mt = 0; mt < 4; mt++) {
            const int m = warpM * 64 + mt * 16 + gid;
            af[mt][0] = As[m][tig];
            af[mt][1] = As[m + 8][tig];
            af[mt][2] = As[m][tig + 4];
            af[mt][3] = As[m + 8][tig + 4];
        }
#pragma unroll
        for (int nt = 0; nt < 4; nt++) {
            const int n = warpN * 32 + nt * 8 + gid;
            bf[nt][0] = Bs[tig][n];
            bf[nt][1] = Bs[tig + 4][n];
        }
#pragma unroll
        for (int mt = 0; mt < 4; mt++)
#pragma unroll
            for (int nt = 0; nt < 4; nt++)
                mma8(acc[mt][nt], af[mt], bf[nt]);

        __syncthreads();   // all reads done
        if (more) {
            uint4 ta = make_uint4(f2tf(nav.x), f2tf(nav.y), f2tf(nav.z), f2tf(nav.w));
            uint4 tb = make_uint4(f2tf(nbv.x), f2tf(nbv.y), f2tf(nbv.z), f2tf(nbv.w));
            *(uint4*)&As[aRow][aCol] = ta;
            *(uint4*)&Bs[bRow][bCol] = tb;
        }
    }

    // epilogue
#pragma unroll
    for (int mt = 0; mt < 4; mt++) {
        const int m0 = rowBase + warpM * 64 + mt * 16 + gid;
#pragma unroll
        for (int nt = 0; nt < 4; nt++) {
            const int n = colBase + warpN * 32 + nt * 8 + 2 * tig;
            const float b0 = bias[n];
            const float b1 = bias[n + 1];
            if (mode == 0) {
                const int seg = n / Ff;              // 0:q 1:k 2:v
                float* dst = (seg == 0) ? g_q : (seg == 1) ? g_k : g_v;
                const int ln = n - seg * Ff;
                *(float2*)(dst + (size_t)m0 * Ff + ln) =
                    make_float2(acc[mt][nt][0] + b0, acc[mt][nt][1] + b1);
                *(float2*)(dst + (size_t)(m0 + 8) * Ff + ln) =
                    make_float2(acc[mt][nt][2] + b0, acc[mt][nt][3] + b1);
            } else {
                *(float2*)(C + (size_t)m0 * N + n) =
                    make_float2(acc[mt][nt][0] + b0, acc[mt][nt][1] + b1);
                *(float2*)(C + (size_t)(m0 + 8) * N + n) =
                    make_float2(acc[mt][nt][2] + b0, acc[mt][nt][3] + b1);
            }
        }
    }
}

// ---------------------------------------------------------------------------
// Kernel 2: TF32 flash attention, causal.
// CTA: 128 q-rows, 8 warps (16 q-rows each), 64-key tiles, D=64.
// Q fragments live in registers for the whole kernel (scale*log2e folded in).
// Smem pitches: Ks/Ps pitch 68 (4b+a distinct), Vs pitch 72 (8a+b distinct)
//   -> all fragment LDS bank-conflict-free.
// ---------------------------------------------------------------------------
#define APQ 68
#define APV 72
#define FLASH_SMEM_U32 (64 * APQ + 64 * APV + 8 * 16 * APQ + 64)
#define FLASH_SMEM_BYTES (FLASH_SMEM_U32 * 4)

__global__ __launch_bounds__(256)
void flash_tf32(const unsigned char* __restrict__ padmask)
{
    extern __shared__ unsigned sm[];
    unsigned* Ks = sm;                       // [64][APQ]
    unsigned* Vs = Ks + 64 * APQ;            // [64][APV]
    unsigned* Ps = Vs + 64 * APV;            // [8 warps][16][APQ]
    float* padAdd = (float*)(Ps + 8 * 16 * APQ);  // [64]

    const int tid  = threadIdx.x;
    const int lane = tid & 31;
    const int w    = tid >> 5;
    const int gid  = lane >> 2;
    const int tig  = lane & 3;

    const int bh = blockIdx.y;
    const int b  = bh / Hh;
    const int h  = bh % Hh;
    const int qt = gridDim.x - 1 - blockIdx.x;      // longest CTAs first
    const int qBase = qt * 128;
    const int qRow0 = qBase + w * 16;

    const float* Qg = g_q + (size_t)b * Ss * Ff + h * Dd;
    const float* Kg = g_k + (size_t)b * Ss * Ff + h * Dd;
    const float* Vg = g_v + (size_t)b * Ss * Ff + h * Dd;

    unsigned* Pw = Ps + w * 16 * APQ;

    // ---- prologue: build Q a-fragments in registers (scale folded) ----
    const float QSCALE = 0.125f * 1.4426950408889634f;   // 1/sqrt(D) * log2(e)
#pragma unroll
    for (int i = 0; i < 8; i++) {
        const int idx = lane + 32 * i;          // 0..255
        const int r   = idx >> 4;               // 0..15
        const int c4  = (idx & 15) * 4;
        float4 v = *(const float4*)(Qg + (size_t)(qRow0 + r) * Ff + c4);
        *(uint4*)&Pw[r * APQ + c4] =
            make_uint4(f2tf(v.x * QSCALE), f2tf(v.y * QSCALE),
                       f2tf(v.z * QSCALE), f2tf(v.w * QSCALE));
    }
    __syncwarp();
    unsigned qa[8][4];
#pragma unroll
    for (int t8 = 0; t8 < 8; t8++) {
        qa[t8][0] = Pw[gid * APQ + 8 * t8 + tig];
        qa[t8][1] = Pw[(gid + 8) * APQ + 8 * t8 + tig];
        qa[t8][2] = Pw[gid * APQ + 8 * t8 + tig + 4];
        qa[t8][3] = Pw[(gid + 8) * APQ + 8 * t8 + tig + 4];
    }

    float o[8][4];
#pragma unroll
    for (int j = 0; j < 8; j++)
#pragma unroll
        for (int r = 0; r < 4; r++) o[j][r] = 0.f;
    float mlo = -1e30f, mhi = -1e30f, llo = 0.f, lhi = 0.f;

    const int nkt = (qBase + 128) / 64;          // causal tile count
#pragma unroll 1
    for (int kt = 0; kt < nkt; kt++) {
        const int kBase = kt * 64;
        __syncthreads();                         // prev tile fully consumed

        // ---- load + convert K, V tiles ----
#pragma unroll
        for (int i = 0; i < 4; i++) {
            const int idx = tid + 256 * i;       // 0..1023
            const int r   = idx >> 4;            // 0..63
            const int c4  = (idx & 15) * 4;
            float4 kv = *(const float4*)(Kg + (size_t)(kBase + r) * Ff + c4);
            *(uint4*)&Ks[r * APQ + c4] =
                make_uint4(f2tf(kv.x), f2tf(kv.y), f2tf(kv.z), f2tf(kv.w));
            float4 vv = *(const float4*)(Vg + (size_t)(kBase + r) * Ff + c4);
            *(uint4*)&Vs[r * APV + c4] =
                make_uint4(f2tf(vv.x), f2tf(vv.y), f2tf(vv.z), f2tf(vv.w));
        }
        if (tid < 64)
            padAdd[tid] = padmask[(size_t)b * Ss + kBase + tid] ? -1e30f : 0.f;
        __syncthreads();

        // warps fully above the diagonal for this key tile do nothing
        const bool active = (kBase <= qRow0 + 15);
        if (active) {
            // ---- S = Q K^T (scaled, log2 domain) ----
            float s[8][4];
#pragma unroll
            for (int j = 0; j < 8; j++)
#pragma unroll
                for (int r = 0; r < 4; r++) s[j][r] = 0.f;

#pragma unroll
            for (int t8 = 0; t8 < 8; t8++) {
#pragma unroll
                for (int j = 0; j < 8; j++) {
                    unsigned bfr[2];
                    bfr[0] = Ks[(8 * j + gid) * APQ + 8 * t8 + tig];
                    bfr[1] = Ks[(8 * j + gid) * APQ + 8 * t8 + tig + 4];
                    mma8(s[j], qa[t8], bfr);
                }
            }

            // ---- padding + causal mask ----
            const int qlo = qRow0 + gid;
            const int qhi = qlo + 8;
            if (kBase + 63 > qRow0) {            // warp-uniform: diagonal tile
#pragma unroll
                for (int j = 0; j < 8; j++) {
                    const float pv0 = padAdd[8 * j + 2 * tig];
                    const float pv1 = padAdd[8 * j + 2 * tig + 1];
                    const int k0 = kBase + 8 * j + 2 * tig;
                    const int k1 = k0 + 1;
                    s[j][0] = (k0 > qlo) ? -1e30f : s[j][0] + pv0;
                    s[j][1] = (k1 > qlo) ? -1e30f : s[j][1] + pv1;
                    s[j][2] = (k0 > qhi) ? -1e30f : s[j][2] + pv0;
                    s[j][3] = (k1 > qhi) ? -1e30f : s[j][3] + pv1;
                }
            } else {
#pragma unroll
                for (int j = 0; j < 8; j++) {
                    const float pv0 = padAdd[8 * j + 2 * tig];
                    const float pv1 = padAdd[8 * j + 2 * tig + 1];
                    s[j][0] += pv0; s[j][1] += pv1;
                    s[j][2] += pv0; s[j][3] += pv1;
                }
            }

            // ---- online softmax (rows owned by 4-lane quads) ----
            float mtlo = -1e30f, mthi = -1e30f;
#pragma unroll
            for (int j = 0; j < 8; j++) {
                mtlo = fmaxf(mtlo, fmaxf(s[j][0], s[j][1]));
                mthi = fmaxf(mthi, fmaxf(s[j][2], s[j][3]));
            }
            mtlo = fmaxf(mtlo, __shfl_xor_sync(0xffffffffu, mtlo, 1));
            mtlo = fmaxf(mtlo, __shfl_xor_sync(0xffffffffu, mtlo, 2));
            mthi = fmaxf(mthi, __shfl_xor_sync(0xffffffffu, mthi, 1));
            mthi = fmaxf(mthi, __shfl_xor_sync(0xffffffffu, mthi, 2));

            const float mnl = fmaxf(mlo, mtlo);
            const float mnh = fmaxf(mhi, mthi);
            const float clo = exp2f(mlo - mnl);
            const float chi = exp2f(mhi - mnh);
            mlo = mnl; mhi = mnh;

            float rslo = 0.f, rshi = 0.f;
#pragma unroll
            for (int j = 0; j < 8; j++) {
                s[j][0] = exp2f(s[j][0] - mnl);
                s[j][1] = exp2f(s[j][1] - mnl);
                s[j][2] = exp2f(s[j][2] - mnh);
                s[j][3] = exp2f(s[j][3] - mnh);
                rslo += s[j][0] + s[j][1];
                rshi += s[j][2] + s[j][3];
            }
            rslo += __shfl_xor_sync(0xffffffffu, rslo, 1);
            rslo += __shfl_xor_sync(0xffffffffu, rslo, 2);
            rshi += __shfl_xor_sync(0xffffffffu, rshi, 1);
            rshi += __shfl_xor_sync(0xffffffffu, rshi, 2);
            llo = llo * clo + rslo;
            lhi = lhi * chi + rshi;
#pragma unroll
            for (int j = 0; j < 8; j++) {
                o[j][0] *= clo; o[j][1] *= clo;
                o[j][2] *= chi; o[j][3] *= chi;
            }

            // ---- P d-frag -> smem -> a-frag; O += P V ----
#pragma unroll
            for (int j = 0; j < 8; j++) {
                *(uint2*)&Pw[gid * APQ + 8 * j + 2 * tig] =
                    make_uint2(f2tf(s[j][0]), f2tf(s[j][1]));
                *(uint2*)&Pw[(gid + 8) * APQ + 8 * j + 2 * tig] =
                    make_uint2(f2tf(s[j][2]), f2tf(s[j][3]));
            }
            __syncwarp();
#pragma unroll
            for (int t8 = 0; t8 < 8; t8++) {
                unsigned pa[4];
                pa[0] = Pw[gid * APQ + 8 * t8 + tig];
                pa[1] = Pw[(gid + 8) * APQ + 8 * t8 + tig];
                pa[2] = Pw[gid * APQ + 8 * t8 + tig + 4];
                pa[3] = Pw[(gid + 8) * APQ + 8 * t8 + tig + 4];
#pragma unroll
                for (int j = 0; j < 8; j++) {
                    unsigned bfr[2];
                    bfr[0] = Vs[(8 * t8 + tig) * APV + 8 * j + gid];
                    bfr[1] = Vs[(8 * t8 + tig + 4) * APV + 8 * j + gid];
                    mma8(o[j], pa, bfr);
                }
            }
        }
    }

    // ---- finalize: O /= l, write [B,S,H,D] ----
    const float ilo = 1.0f / llo;
    const float ihi = 1.0f / lhi;
    const int qlo = qRow0 + gid;
    float* Og = g_attn + (size_t)b * Ss * Ff + h * Dd;
#pragma unroll
    for (int j = 0; j < 8; j++) {
        const int d = 8 * j + 2 * tig;
        *(float2*)(Og + (size_t)qlo * Ff + d) =
            make_float2(o[j][0] * ilo, o[j][1] * ilo);
        *(float2*)(Og + (size_t)(qlo + 8) * Ff + d) =
            make_float2(o[j][2] * ihi, o[j][3] * ihi);
    }
}

// ---------------------------------------------------------------------------
// Launch: QKV gemm -> flash attention -> output gemm (one default stream)
// ---------------------------------------------------------------------------
extern "C" void kernel_launch(void* const* d_in, const int* in_sizes, int n_in,
                              void* d_out, int out_size)
{
    (void)in_sizes; (void)n_in; (void)out_size;
    const float*         x    = (const float*)d_in[0];
    const unsigned char* pad  = (const unsigned char*)d_in[1];
    const float*         Wqkv = (const float*)d_in[2];
    const float*         bqkv = (const float*)d_in[3];
    const float*         Wout = (const float*)d_in[4];
    const float*         bout = (const float*)d_in[5];
    float*               out  = (float*)d_out;

    // 1) QKV projection (tf32): [8192,768] @ [768,2304] -> g_q/g_k/g_v
    {
        dim3 grid(NQKV / 128, ROWS / 128);   // (18, 64)
        gemm_tf32<<<grid, 256>>>(x, Wqkv, bqkv, nullptr, Ff, NQKV, 0);
    }

    // 2) causal flash attention (tf32 mma) -> g_attn
    {
        cudaFuncSetAttribute(flash_tf32,
                             cudaFuncAttributeMaxDynamicSharedMemorySize,
                             FLASH_SMEM_BYTES);
        dim3 grid(Ss / 128, Bb * Hh);        // (32, 24)
        flash_tf32<<<grid, 256, FLASH_SMEM_BYTES>>>(pad);
    }

    // 3) output projection (tf32): g_attn @ Wout + bout -> d_out
    {
        float* attnPtr = nullptr;
        cudaGetSymbolAddress((void**)&attnPtr, g_attn);
        dim3 grid(Ff / 128, ROWS / 128);     // (6, 64)
        gemm_tf32<<<grid, 256>>>(attnPtr, Wout, bout, out, Ff, Ff, 1);
    }
}